// round 10
// baseline (speedup 1.0000x reference)
#include <cuda_runtime.h>
#include <math.h>

#define EPS_F 1e-6f
#define NCOL 64
#define LSTEP 63

// Per-launch derived parameters (written by block 0, read by all blocks).
__device__ __align__(16) float g_coef[NCOL];  // log-domain coefficients (geo fast path)
__device__ int   g_all_geo;                   // 1 if every step is the geometric branch
__device__ float g_a[LSTEP];                  // a_vec (NaN replacement value)
__device__ float g_r[LSTEP];                  // power-mean exponent r
__device__ float g_wacc[LSTEP];
__device__ float g_wnew[LSTEP];
__device__ int   g_geo[LSTEP];                // per-step geo flag (generic path)
__device__ int   g_flag;                      // release flag (zero-initialized)
// NOTE on replays: g_flag stays 1 after the first launch, but block 0 rewrites
// bit-identical coefficient values every launch (deterministic function of the
// inputs), so a reader racing the rewrite observes identical bytes. The very
// first launch has g_flag==0 and is strictly ordered.

__device__ __forceinline__ float clip01(float v) {
    return fminf(fmaxf(v, EPS_F), 1.0f);
}

// log2 term for the fast path. Reference clips x to [EPS, 1]; the input domain
// is [0,1) so only the EPS floor can bind.
__device__ __forceinline__ float lg2c(float v) {
    return __log2f(fmaxf(v, EPS_F));
}

// Generic single aggregation step (slow path, semantics-exact)
__device__ float aggregate_step(float acc, float right, int i) {
    float acc_c = clip01(acc);
    float rc    = clip01(right);
    if (g_geo[i]) {
        return powf(acc_c, g_wacc[i]) * powf(rc, g_wnew[i]);
    }
    float r = g_r[i];
    return powf(g_wacc[i] * powf(acc_c, r) + g_wnew[i] * powf(rc, r), 1.0f / r);
}

__device__ __forceinline__ float dot8_log(const float4& v0, const float4& v1,
                                          const float4& c0, const float4& c1) {
    float s;
    s = c0.x * lg2c(v0.x);
    s = fmaf(c0.y, lg2c(v0.y), s);
    s = fmaf(c0.z, lg2c(v0.z), s);
    s = fmaf(c0.w, lg2c(v0.w), s);
    s = fmaf(c1.x, lg2c(v1.x), s);
    s = fmaf(c1.y, lg2c(v1.y), s);
    s = fmaf(c1.z, lg2c(v1.z), s);
    s = fmaf(c1.w, lg2c(v1.w), s);
    return s;
}

// Single kernel. Block 0 computes the parameters (fully parallel, 64 threads)
// and releases g_flag; all other blocks prefetch their x-loads FIRST and then
// spin (one thread per block) on the flag — the spin hides under DRAM latency
// for wave 0 and is a single already-set atomic read for later waves.
// Main body (validated R5/R9): 8 lanes per row, 2 rows per thread (i, i+B/2);
// lane s loads float4 index s and s+8 — every warp-LDG.128 covers 4 fully-
// contiguous 128B lines; MLP=4.
__global__ void __launch_bounds__(256, 8)
vln_kernel(const float* __restrict__ x,
           const float* __restrict__ a_raw,
           const float* __restrict__ w_raw,
           float* __restrict__ out, int B) {
    const int t    = threadIdx.x;
    const int gtid = blockIdx.x * blockDim.x + t;
    const int half = B >> 1;
    const int i    = gtid >> 3;
    const int s    = gtid & 7;

    const bool active = (i < half);
    const int  rowA   = active ? i : 0;
    const int  rowB   = active ? (i + half) : 0;

    const float4* pa = reinterpret_cast<const float4*>(x + (size_t)rowA * NCOL);
    const float4* pb = reinterpret_cast<const float4*>(x + (size_t)rowB * NCOL);

    // ---- 1) front-batched independent loads (MLP=4), parameter-independent
    float4 a0 = __ldg(pa + s);
    float4 a1 = __ldg(pa + s + 8);
    float4 b0 = __ldg(pb + s);
    float4 b1 = __ldg(pb + s + 8);

    // ---- 2) parameters: block 0 computes + releases; others acquire --------
    if (blockIdx.x == 0) {
        __shared__ float s_mn[2], s_mx[2], s_S32;
        const int  lane = t & 31;
        const int  wid  = t >> 5;
        const bool pt   = (t < LSTEP);
        const bool in64 = (t < 64);

        float w  = pt ? __ldg(w_raw + t) : 0.0f;
        float ar = pt ? __ldg(a_raw + t) : 0.0f;

        if (in64) {
            float lo = pt ? w :  3.0e38f;
            float hi = pt ? w : -3.0e38f;
#pragma unroll
            for (int d = 16; d; d >>= 1) {
                lo = fminf(lo, __shfl_xor_sync(0xFFFFFFFFu, lo, d));
                hi = fmaxf(hi, __shfl_xor_sync(0xFFFFFFFFu, hi, d));
            }
            if (lane == 0) { s_mn[wid] = lo; s_mx[wid] = hi; }
        }
        __syncthreads();

        float wnv = 0.0f, wav = 1.0f;
        int geov = 1;
        if (pt) {
            float wmin  = fminf(s_mn[0], s_mn[1]);
            float denom = fmaxf(fmaxf(s_mx[0], s_mx[1]) - wmin, 1e-8f);
            float a   = 3.0f / (1.0f + expf(-ar)) - 1.0f;
            float a_c = fminf(fmaxf(a, EPS_F), 1.0f - EPS_F);
            float r   = (1.0f - 2.0f * a_c) / (a_c * (1.0f - a_c));
            geov = fabsf(r) < 0.001f;
            wnv  = fminf(fmaxf((w - wmin) / denom, 0.0f), 1.0f);
            wav  = 1.0f - wnv;
            g_a[t]    = a;
            g_r[t]    = r;
            g_wnew[t] = wnv;
            g_wacc[t] = wav;
            g_geo[t]  = geov;
        }

        // inclusive suffix-product scan of wacc within each warp (t=63 -> 1)
        float S = pt ? wav : 1.0f;
        if (in64) {
#pragma unroll
            for (int d = 1; d < 32; d <<= 1) {
                float v = __shfl_down_sync(0xFFFFFFFFu, S, d);
                if (lane + d < 32) S *= v;
            }
            if (wid == 1 && lane == 0) s_S32 = S;   // prod_{32..62}
        }
        int allgeo = __syncthreads_and(pt ? geov : 1);
        if (t == 0) g_all_geo = allgeo;

        if (in64) {
            float E;  // exclusive suffix product E_t = prod_{i>t} wacc_i
            if (wid == 0) {
                float S32 = s_S32;
                S *= S32;                                 // full inclusive suffix
                E = __shfl_down_sync(0xFFFFFFFFu, S, 1);
                if (lane == 31) E = S32;                  // E_31 = prod_{32..62}
            } else {
                E = __shfl_down_sync(0xFFFFFFFFu, S, 1);
                if (lane == 31) E = 1.0f;                 // t=63 unused
            }
            if (pt) {
                g_coef[t + 1] = wnv * E;                  // c_{t+1} = wnew_t * P[t+1]
                if (t == 0) g_coef[0] = wav * E;          // c_0 = wacc_0 * P[1]
            }
            __threadfence();                              // release writers' stores
        }
        __syncthreads();
        if (t == 0) atomicExch(&g_flag, 1);               // release flag
        // block 0's own threads see the stores via the __syncthreads above
    } else {
        if (t == 0) {
            while (atomicAdd(&g_flag, 0) == 0) { }
            __threadfence();                              // acquire
        }
        __syncthreads();
    }

    // ---- 3) main computation ----------------------------------------------
    if (!active) return;

    if (g_all_geo) {
        const float4* pc = reinterpret_cast<const float4*>(g_coef);
        float4 c0 = pc[s];
        float4 c1 = pc[s + 8];

        float sa = dot8_log(a0, a1, c0, c1);
        float sb = dot8_log(b0, b1, c0, c1);

        sa += __shfl_xor_sync(0xFFFFFFFFu, sa, 4);
        sb += __shfl_xor_sync(0xFFFFFFFFu, sb, 4);
        sa += __shfl_xor_sync(0xFFFFFFFFu, sa, 2);
        sb += __shfl_xor_sync(0xFFFFFFFFu, sb, 2);
        sa += __shfl_xor_sync(0xFFFFFFFFu, sa, 1);
        sb += __shfl_xor_sync(0xFFFFFFFFu, sb, 1);

        if (s == 0) {
            out[rowA] = exp2f(sa);
            out[rowB] = exp2f(sb);
        }
    } else {
        // Generic sequential path (unused for these inputs): leader walks rows.
        if (s == 0) {
            int rows[2] = {rowA, rowB};
#pragma unroll
            for (int q = 0; q < 2; q++) {
                const float* xr = x + (size_t)rows[q] * NCOL;
                float acc = aggregate_step(xr[0], xr[1], 0);
                for (int k = 1; k < LSTEP; k++) {
                    float z = aggregate_step(acc, xr[k + 1], k);
                    if (isnan(z)) z = g_a[k];
                    acc = z;
                }
                out[rows[q]] = acc;
            }
        }
    }
}

extern "C" void kernel_launch(void* const* d_in, const int* in_sizes, int n_in,
                              void* d_out, int out_size) {
    const float* x     = (const float*)d_in[0];
    const float* a_raw = (const float*)d_in[1];
    const float* w_raw = (const float*)d_in[2];
    float* out = (float*)d_out;

    int B = in_sizes[0] / NCOL;   // B is even for this problem (524288)

    long long total_threads = ((long long)B / 2) * 8;
    int threads = 256;
    int blocks  = (int)((total_threads + threads - 1) / threads);

    vln_kernel<<<blocks, threads>>>(x, a_raw, w_raw, out, B);
}